// round 17
// baseline (speedup 1.0000x reference)
#include <cuda_runtime.h>
#include <float.h>

// ChamferDist (adv->ori): loss = mean_b( w_b * mean_k( min_j ||adv[bk]-ori[bj]||^2 ) )
//
// R17: ALGORITHMIC pruning. Brute force hit its issued-instruction floor
// (~12M warp-instrs, ~28us plateau across all scheduling levers R13-R16).
// min_j admits pruning: sort ori by x into 256 bins (counting sort per batch);
// per adv point, evaluate bins outward from own bin; stop a side when the
// bin-edge dx^2 (with one-bin fp-safety slack) exceeds current best. Every
// skipped point provably has dist >= best >= final -> EXACT same min as the
// full scan (same per-candidate math as R12, which passed rel_err 0.0).
// Deterministic: min is order-invariant; all sums fixed-order.
//
// Kernel A (8 CTAs): per-batch x-bbox, 256-bin count/scan/scatter ->
//   sorted pts (-2x,-2y,-2z,b2) + bin_start in global scratch (rewritten
//   every call -> graph-replay safe).
// Kernel B (B*K/256 CTAs): smem-cache batch pts (64KB) + bin_start; per
//   thread pruned search; CTA reduce -> partial; counter -> last CTA sums.

#define CDQ_THREADS 256
#define CDB_THREADS 256
#define CD_NBINS    256
#define CD_MAX_PTS  (1 << 17)    // max B*K
#define CD_MAX_B    64
#define CD_MAX_BLOCKS 4096

__device__ float4       g_cd_pts[CD_MAX_PTS];            // sorted transformed ori
__device__ int          g_cd_binstart[CD_MAX_B * (CD_NBINS + 1)];
__device__ float        g_cd_grid[CD_MAX_B * 2];         // lo, binw per batch
__device__ float        g_cd_partial[CD_MAX_BLOCKS];
__device__ unsigned int g_cd_final_count;

// ---------------- Build: per-batch counting sort by x ----------------
__global__ __launch_bounds__(CDB_THREADS)
void chamfer_build_kernel(const float* __restrict__ ori, int K) {
    __shared__ float sred[CDB_THREADS / 32];
    __shared__ int   scnt[CD_NBINS];
    __shared__ int   sscan[CD_NBINS];
    __shared__ int   scur[CD_NBINS];
    __shared__ float sLo, sInv, sBw;

    const int b   = blockIdx.x;
    const int tid = threadIdx.x;
    const int lane = tid & 31, wid = tid >> 5;
    const float* __restrict__ orib = ori + (size_t)b * K * 3;

    // ---- x min/max reduce ----
    float lo = FLT_MAX, hi = -FLT_MAX;
    for (int j = tid; j < K; j += CDB_THREADS) {
        const float x = orib[3 * j];
        lo = fminf(lo, x); hi = fmaxf(hi, x);
    }
#pragma unroll
    for (int off = 16; off > 0; off >>= 1) {
        lo = fminf(lo, __shfl_down_sync(0xffffffffu, lo, off));
        hi = fmaxf(hi, __shfl_down_sync(0xffffffffu, hi, off));
    }
    if (lane == 0) sred[wid] = lo;
    __syncthreads();
    if (tid == 0) {
        float v = FLT_MAX;
        for (int i = 0; i < CDB_THREADS / 32; ++i) v = fminf(v, sred[i]);
        sLo = v;
    }
    __syncthreads();
    if (lane == 0) sred[wid] = hi;
    __syncthreads();
    if (tid == 0) {
        float v = -FLT_MAX;
        for (int i = 0; i < CDB_THREADS / 32; ++i) v = fmaxf(v, sred[i]);
        const float range = v - sLo;
        if (range > 1e-30f) { sInv = (float)CD_NBINS / range; sBw = range / (float)CD_NBINS; }
        else                { sInv = 0.0f;                    sBw = 0.0f; }
        g_cd_grid[2 * b + 0] = sLo;
        g_cd_grid[2 * b + 1] = sBw;
    }
    __syncthreads();

    // ---- count ----
    if (tid < CD_NBINS) scnt[tid] = 0;
    __syncthreads();
    for (int j = tid; j < K; j += CDB_THREADS) {
        int bin = (int)floorf((orib[3 * j] - sLo) * sInv);
        bin = bin < 0 ? 0 : (bin > CD_NBINS - 1 ? CD_NBINS - 1 : bin);
        atomicAdd(&scnt[bin], 1);
    }
    __syncthreads();

    // ---- exclusive scan (Hillis-Steele inclusive, then shift) ----
    if (tid < CD_NBINS) sscan[tid] = scnt[tid];
    __syncthreads();
    for (int off = 1; off < CD_NBINS; off <<= 1) {
        int v = 0;
        if (tid < CD_NBINS && tid >= off) v = sscan[tid - off];
        __syncthreads();
        if (tid < CD_NBINS) sscan[tid] += v;
        __syncthreads();
    }
    int* __restrict__ bs = g_cd_binstart + b * (CD_NBINS + 1);
    if (tid < CD_NBINS) {
        const int excl = sscan[tid] - scnt[tid];
        bs[tid]   = excl;
        scur[tid] = excl;
    }
    if (tid == 0) bs[CD_NBINS] = K;
    __syncthreads();

    // ---- scatter (transformed) ----
    float4* __restrict__ dst = g_cd_pts + (size_t)b * K;
    for (int j = tid; j < K; j += CDB_THREADS) {
        const float x = orib[3 * j + 0];
        const float y = orib[3 * j + 1];
        const float z = orib[3 * j + 2];
        int bin = (int)floorf((x - sLo) * sInv);
        bin = bin < 0 ? 0 : (bin > CD_NBINS - 1 ? CD_NBINS - 1 : bin);
        const int pos = atomicAdd(&scur[bin], 1);
        dst[pos] = make_float4(-2.0f * x, -2.0f * y, -2.0f * z,
                               x * x + y * y + z * z);
    }
}

// ---------------- Query: pruned nearest search ----------------
__global__ __launch_bounds__(CDQ_THREADS)
void chamfer_query_kernel(const float* __restrict__ adv,
                          const float* __restrict__ w,
                          float* __restrict__ out,
                          int B, int K, int tilesPerB, float scale) {
    extern __shared__ char smem_raw[];
    __shared__ float red[CDQ_THREADS / 32];
    __shared__ bool  sFlag;

    const int tid  = threadIdx.x;
    const int tile = blockIdx.x % tilesPerB;
    const int b    = blockIdx.x / tilesPerB;
    const int nblocks = B * tilesPerB;

    const float4* __restrict__ gpts = g_cd_pts + (size_t)b * K;
    const int*    __restrict__ gbs  = g_cd_binstart + b * (CD_NBINS + 1);
    const float lo = g_cd_grid[2 * b + 0];
    const float bw = g_cd_grid[2 * b + 1];
    const float inv = (bw > 0.0f) ? (1.0f / bw) : 0.0f;

    // smem cache when it fits (K*16 + (NBINS+1)*4 bytes)
    const bool useSmem = ((size_t)K * 16 <= 80 * 1024);
    float4* sp = (float4*)smem_raw;
    int*    sb = (int*)(smem_raw + (size_t)K * 16);
    if (useSmem) {
        for (int i = tid; i < K; i += CDQ_THREADS) sp[i] = gpts[i];
        for (int i = tid; i <= CD_NBINS; i += CDQ_THREADS) sb[i] = gbs[i];
    }
    __syncthreads();
    const float4* __restrict__ P  = useSmem ? sp : gpts;
    const int*    __restrict__ BS = useSmem ? sb : gbs;

    const int k = tile * CDQ_THREADS + tid;
    float local = 0.0f;
    if (k < K) {
        const float* __restrict__ a = adv + ((size_t)b * K + k) * 3;
        const float ax = a[0], ay = a[1], az = a[2];
        const float a2 = ax * ax + ay * ay + az * az;

        int pb = (int)floorf((ax - lo) * inv);
        pb = pb < 0 ? 0 : (pb > CD_NBINS - 1 ? CD_NBINS - 1 : pb);

        float best = FLT_MAX;   // min of (b2 - 2 a.o)  == dist - a2

        // evaluate own bin
        {
            const int s = BS[pb], e = BS[pb + 1];
            for (int i = s; i < e; ++i) {
                const float4 o = P[i];
                float t = fmaf(az, o.z, o.w);
                t = fmaf(ay, o.y, t);
                t = fmaf(ax, o.x, t);
                best = fminf(best, t);
            }
        }

        // expand outward; stop a side when safe edge-dx^2 > best + a2... note:
        // best is (dist - a2); excluded points have dist >= dx^2, i.e.
        // (b2-2ab) >= dx^2 - a2. So compare dx^2 - a2 > best.
        int l = pb - 1, r = pb + 1;
        const float DONE = FLT_MAX;
        while (l >= 0 || r < CD_NBINS) {
            // safe squared x-distance to each side's next bin (1-bin slack)
            float dl = DONE, dr = DONE;
            if (l >= 0) {
                const float e = lo + (float)(l + 1) * bw;        // right edge of bin l
                float d = ax - e; d = fmaxf(0.0f, d - bw);       // slack
                dl = d * d;
            }
            if (r < CD_NBINS) {
                const float e = lo + (float)r * bw;              // left edge of bin r
                float d = e - ax; d = fmaxf(0.0f, d - bw);       // slack
                dr = d * d;
            }
            if (dl <= dr) {
                if (l < 0 || dl - a2 > best) { if (dr == DONE || dr - a2 > best) break; l = -1; continue; }
                const int s = BS[l], e2 = BS[l + 1];
                for (int i = s; i < e2; ++i) {
                    const float4 o = P[i];
                    float t = fmaf(az, o.z, o.w);
                    t = fmaf(ay, o.y, t);
                    t = fmaf(ax, o.x, t);
                    best = fminf(best, t);
                }
                --l;
            } else {
                if (dr - a2 > best) { if (dl == DONE || dl - a2 > best) break; r = CD_NBINS; continue; }
                const int s = BS[r], e2 = BS[r + 1];
                for (int i = s; i < e2; ++i) {
                    const float4 o = P[i];
                    float t = fmaf(az, o.z, o.w);
                    t = fmaf(ay, o.y, t);
                    t = fmaf(ax, o.x, t);
                    best = fminf(best, t);
                }
                ++r;
            }
        }
        local = best + a2;
    }

    // ---- CTA fixed-order reduction ----
    const int lane = tid & 31, wid = tid >> 5;
#pragma unroll
    for (int off = 16; off > 0; off >>= 1)
        local += __shfl_down_sync(0xffffffffu, local, off);
    if (lane == 0) red[wid] = local;
    __syncthreads();
    if (tid == 0) {
        float v = 0.0f;
#pragma unroll
        for (int i = 0; i < CDQ_THREADS / 32; ++i) v += red[i];
        g_cd_partial[blockIdx.x] = v * w[b];
    }

    // ---- last-CTA finalize ----
    __threadfence();
    if (tid == 0) {
        const unsigned int c = atomicAdd(&g_cd_final_count, 1u);
        sFlag = (c == (unsigned int)(nblocks - 1));
    }
    __syncthreads();
    if (!sFlag) return;
    __threadfence();

    float s2 = 0.0f;
    for (int i = tid; i < nblocks; i += CDQ_THREADS)
        s2 += g_cd_partial[i];
#pragma unroll
    for (int off = 16; off > 0; off >>= 1)
        s2 += __shfl_down_sync(0xffffffffu, s2, off);
    if (lane == 0) red[wid] = s2;
    __syncthreads();
    if (tid == 0) {
        float v = 0.0f;
#pragma unroll
        for (int i = 0; i < CDQ_THREADS / 32; ++i) v += red[i];
        out[0] = v * scale;
        g_cd_final_count = 0u;   // reset for graph replay
    }
}

extern "C" void kernel_launch(void* const* d_in, const int* in_sizes, int n_in,
                              void* d_out, int out_size) {
    const float* adv = (const float*)d_in[0];   // [B, K, 3] float32
    const float* ori = (const float*)d_in[1];   // [B, K, 3] float32
    const float* w   = (const float*)d_in[2];   // [B]       float32
    float* out = (float*)d_out;                 // scalar float32

    const int B = in_sizes[2];
    const int K = in_sizes[0] / (3 * B);

    chamfer_build_kernel<<<B, CDB_THREADS>>>(ori, K);

    const int tilesPerB = (K + CDQ_THREADS - 1) / CDQ_THREADS;
    const int blocks = B * tilesPerB;           // 8*16 = 128 @ B=8,K=4096

    size_t smem = 0;
    if ((size_t)K * 16 <= 80 * 1024)
        smem = (size_t)K * 16 + (CD_NBINS + 1) * sizeof(int);
    cudaFuncSetAttribute(chamfer_query_kernel,
                         cudaFuncAttributeMaxDynamicSharedMemorySize,
                         (int)(smem > 0 ? smem : 0));

    const float scale = 1.0f / ((float)B * (float)K);
    chamfer_query_kernel<<<blocks, CDQ_THREADS, smem>>>(adv, w, out,
                                                        B, K, tilesPerB, scale);
}